// round 1
// baseline (speedup 1.0000x reference)
#include <cuda_runtime.h>

#define NNODES 1000000
#define NGRAPHS 16384
#define NF 128          // node features
#define GF 64           // global features
#define HID 64          // hidden

// Scratch (no allocations allowed -> device globals)
__device__ float g_U[NGRAPHS * HID];   // u @ W1u + b1
__device__ float g_s[NNODES];          // per-node score
__device__ int   g_seg[NGRAPHS + 1];   // segment offsets (batch is sorted)

// ---------------------------------------------------------------------------
// Segment starts via binary search (batch is sorted ascending)
// ---------------------------------------------------------------------------
__global__ void k_segstart(const int* __restrict__ batch, int n) {
    int g = blockIdx.x * blockDim.x + threadIdx.x;
    if (g > NGRAPHS) return;
    int lo = 0, hi = n;
    while (lo < hi) {
        int mid = (lo + hi) >> 1;
        if (batch[mid] < g) lo = mid + 1; else hi = mid;
    }
    g_seg[g] = lo;
}

// ---------------------------------------------------------------------------
// U[g,:] = u[g,:] @ W1[128:192,:] + b1     (one block of 64 threads per graph)
// ---------------------------------------------------------------------------
__global__ void k_uproj(const float* __restrict__ u, const float* __restrict__ W1,
                        const float* __restrict__ b1) {
    int g = blockIdx.x;
    int j = threadIdx.x;           // 0..63
    __shared__ float us[GF];
    us[j] = u[g * GF + j];
    __syncthreads();
    float acc = b1[j];
#pragma unroll 8
    for (int k = 0; k < GF; k++)
        acc = fmaf(us[k], W1[(NF + k) * HID + j], acc);
    g_U[g * HID + j] = acc;
}

// ---------------------------------------------------------------------------
// Per-node MLP score:  s[n] = W2 . relu( x[n] @ W1x + U[batch[n]] ) + b2
// One thread per node; x row in registers; W1x^T staged in shared (broadcast
// LDS.128 reads); 4 independent h-accumulators for FFMA ILP.
// ---------------------------------------------------------------------------
__global__ __launch_bounds__(128, 2)
void k_mlp(const float* __restrict__ x, const float* __restrict__ W1,
           const float* __restrict__ W2, const float* __restrict__ b2,
           const int* __restrict__ batch, int n) {
    __shared__ float sW[HID * NF];   // sW[j*128 + k] = W1[k*64 + j]
    __shared__ float sW2[HID];
    for (int i = threadIdx.x; i < HID * NF; i += 128) {
        int j = i >> 7;        // /128
        int k = i & 127;
        sW[i] = W1[k * HID + j];
    }
    if (threadIdx.x < HID) sW2[threadIdx.x] = W2[threadIdx.x];
    __syncthreads();

    int node = blockIdx.x * 128 + threadIdx.x;
    if (node >= n) return;

    // load x row (128 floats) into registers
    float4 xr[32];
    const float4* xrow = (const float4*)(x + (size_t)node * NF);
#pragma unroll
    for (int i = 0; i < 32; i++) xr[i] = xrow[i];

    int g = batch[node];
    const float4* U4 = (const float4*)(g_U + g * HID);
    const float4* W4 = (const float4*)sW;

    float sacc = b2[0];
#pragma unroll 1
    for (int j4 = 0; j4 < 16; j4++) {
        float4 uu = U4[j4];
        float h0 = uu.x, h1 = uu.y, h2 = uu.z, h3 = uu.w;
        const float4* w0p = W4 + (4 * j4 + 0) * 32;
        const float4* w1p = W4 + (4 * j4 + 1) * 32;
        const float4* w2p = W4 + (4 * j4 + 2) * 32;
        const float4* w3p = W4 + (4 * j4 + 3) * 32;
#pragma unroll
        for (int k4 = 0; k4 < 32; k4++) {
            float4 a  = xr[k4];
            float4 w0 = w0p[k4];
            float4 w1 = w1p[k4];
            float4 w2 = w2p[k4];
            float4 w3 = w3p[k4];
            h0 = fmaf(a.x, w0.x, h0); h0 = fmaf(a.y, w0.y, h0);
            h0 = fmaf(a.z, w0.z, h0); h0 = fmaf(a.w, w0.w, h0);
            h1 = fmaf(a.x, w1.x, h1); h1 = fmaf(a.y, w1.y, h1);
            h1 = fmaf(a.z, w1.z, h1); h1 = fmaf(a.w, w1.w, h1);
            h2 = fmaf(a.x, w2.x, h2); h2 = fmaf(a.y, w2.y, h2);
            h2 = fmaf(a.z, w2.z, h2); h2 = fmaf(a.w, w2.w, h2);
            h3 = fmaf(a.x, w3.x, h3); h3 = fmaf(a.y, w3.y, h3);
            h3 = fmaf(a.z, w3.z, h3); h3 = fmaf(a.w, w3.w, h3);
        }
        sacc = fmaf(sW2[4 * j4 + 0], fmaxf(h0, 0.f), sacc);
        sacc = fmaf(sW2[4 * j4 + 1], fmaxf(h1, 0.f), sacc);
        sacc = fmaf(sW2[4 * j4 + 2], fmaxf(h2, 0.f), sacc);
        sacc = fmaf(sW2[4 * j4 + 3], fmaxf(h3, 0.f), sacc);
    }
    g_s[node] = sacc;
}

// ---------------------------------------------------------------------------
// Per-graph: softmax over segment + attention write + weighted pool.
// One block of 128 threads per graph (thread = feature in pool phase).
// batch sorted -> segment is contiguous [seg[g], seg[g+1]).
// ---------------------------------------------------------------------------
__global__ void k_pool(const float* __restrict__ x,
                       float* __restrict__ pooled, float* __restrict__ attn) {
    int g   = blockIdx.x;
    int tid = threadIdx.x;                 // 0..127
    int s0 = g_seg[g], s1 = g_seg[g + 1];
    __shared__ float red[128];

    // pass 1: segment max
    float m = -3.0e38f;
    for (int i = s0 + tid; i < s1; i += 128) m = fmaxf(m, g_s[i]);
    red[tid] = m; __syncthreads();
#pragma unroll
    for (int off = 64; off > 0; off >>= 1) {
        if (tid < off) red[tid] = fmaxf(red[tid], red[tid + off]);
        __syncthreads();
    }
    m = red[0];
    __syncthreads();

    // pass 2: segment sum of exp
    float z = 0.f;
    for (int i = s0 + tid; i < s1; i += 128) z += __expf(g_s[i] - m);
    red[tid] = z; __syncthreads();
#pragma unroll
    for (int off = 64; off > 0; off >>= 1) {
        if (tid < off) red[tid] += red[tid + off];
        __syncthreads();
    }
    z = red[0];
    float inv = (s1 > s0) ? 1.0f / z : 0.f;
    __syncthreads();

    // attn output (coalesced-ish over segment)
    for (int i = s0 + tid; i < s1; i += 128)
        attn[i] = __expf(g_s[i] - m) * inv;

    // weighted pool: thread tid owns feature tid
    float acc = 0.f;
    for (int nn = s0; nn < s1; nn++) {
        float a = __expf(g_s[nn] - m) * inv;     // broadcast s read (L1-hot)
        acc = fmaf(x[(size_t)nn * NF + tid], a, acc);
    }
    pooled[g * NF + tid] = acc;
}

// ---------------------------------------------------------------------------
extern "C" void kernel_launch(void* const* d_in, const int* in_sizes, int n_in,
                              void* d_out, int out_size) {
    const float* x     = (const float*)d_in[0];   // [1e6, 128]
    const float* u     = (const float*)d_in[1];   // [16384, 64]
    const int*   batch = (const int*)  d_in[2];   // [1e6] sorted
    const float* W1    = (const float*)d_in[3];   // [192, 64]
    const float* b1    = (const float*)d_in[4];   // [64]
    const float* W2    = (const float*)d_in[5];   // [64]
    const float* b2    = (const float*)d_in[6];   // [1]

    float* pooled = (float*)d_out;                     // [16384, 128]
    float* attn   = (float*)d_out + NGRAPHS * NF;      // [1e6]

    int n = in_sizes[2];   // number of nodes

    k_segstart<<<(NGRAPHS + 1 + 255) / 256, 256>>>(batch, n);
    k_uproj<<<NGRAPHS, GF>>>(u, W1, b1);
    k_mlp<<<(n + 127) / 128, 128>>>(x, W1, W2, b2, batch, n);
    k_pool<<<NGRAPHS, 128>>>(x, pooled, attn);
}

// round 3
// speedup vs baseline: 3.1702x; 3.1702x over previous
#include <cuda_runtime.h>
#include <cuda_bf16.h>
#include <cstdint>

#define NNODES 1000000
#define NGRAPHS 16384
#define NF 128          // node features (= K of GEMM)
#define GF 64           // global features
#define HID 64          // hidden (= N of GEMM)

// ---------------------------------------------------------------------------
// Scratch (device globals — no allocations allowed)
// ---------------------------------------------------------------------------
__device__ float g_U[NGRAPHS * HID];   // u @ W1u + b1
__device__ float g_s[NNODES];          // per-node score
__device__ int   g_seg[NGRAPHS + 1];   // segment offsets (batch is sorted)

// ---------------------------------------------------------------------------
// Segment starts via binary search (batch is sorted ascending)
// ---------------------------------------------------------------------------
__global__ void k_segstart(const int* __restrict__ batch, int n) {
    int g = blockIdx.x * blockDim.x + threadIdx.x;
    if (g > NGRAPHS) return;
    int lo = 0, hi = n;
    while (lo < hi) {
        int mid = (lo + hi) >> 1;
        if (batch[mid] < g) lo = mid + 1; else hi = mid;
    }
    g_seg[g] = lo;
}

// ---------------------------------------------------------------------------
// U[g,:] = u[g,:] @ W1[128:192,:] + b1
// ---------------------------------------------------------------------------
__global__ void k_uproj(const float* __restrict__ u, const float* __restrict__ W1,
                        const float* __restrict__ b1) {
    int g = blockIdx.x;
    int j = threadIdx.x;
    __shared__ float us[GF];
    us[j] = u[g * GF + j];
    __syncthreads();
    float acc = b1[j];
#pragma unroll 8
    for (int k = 0; k < GF; k++)
        acc = fmaf(us[k], W1[(NF + k) * HID + j], acc);
    g_U[g * HID + j] = acc;
}

// ---------------------------------------------------------------------------
// bf16 hi/lo split helpers (packed pairs: low 16 bits = lower-k element)
// ---------------------------------------------------------------------------
__device__ __forceinline__ uint32_t pack_hi(float f0, float f1) {
    __nv_bfloat16 h0 = __float2bfloat16(f0);
    __nv_bfloat16 h1 = __float2bfloat16(f1);
    return ((uint32_t)__bfloat16_as_ushort(h1) << 16) | (uint32_t)__bfloat16_as_ushort(h0);
}
__device__ __forceinline__ uint32_t pack_lo(float f0, float f1) {
    __nv_bfloat16 h0 = __float2bfloat16(f0);
    __nv_bfloat16 h1 = __float2bfloat16(f1);
    float l0 = f0 - __bfloat162float(h0);
    float l1 = f1 - __bfloat162float(h1);
    __nv_bfloat16 g0 = __float2bfloat16(l0);
    __nv_bfloat16 g1 = __float2bfloat16(l1);
    return ((uint32_t)__bfloat16_as_ushort(g1) << 16) | (uint32_t)__bfloat16_as_ushort(g0);
}

__device__ __forceinline__ void mma16816(float c[4], const uint32_t a[4],
                                         uint32_t b0, uint32_t b1) {
    asm volatile(
        "mma.sync.aligned.m16n8k16.row.col.f32.bf16.bf16.f32 "
        "{%0,%1,%2,%3}, {%4,%5,%6,%7}, {%8,%9}, {%0,%1,%2,%3};"
        : "+f"(c[0]), "+f"(c[1]), "+f"(c[2]), "+f"(c[3])
        : "r"(a[0]), "r"(a[1]), "r"(a[2]), "r"(a[3]), "r"(b0), "r"(b1));
}

// ---------------------------------------------------------------------------
// Tensor-core MLP via mma.sync (sm_103 base target — no tcgen05):
//   s[n] = W2 . relu( x[n] @ W1x + U[batch[n]] ) + b2
// Block = 128 threads = 4 warps; warp handles 32 rows; tile = 128 rows.
// Split-bf16 x3 terms: ah*bh + al*bh + ah*bl, fp32 accumulators.
// Persistent grid; B fragments precomputed in smem in fragment order.
// ---------------------------------------------------------------------------
struct SmemMMA {
    uint32_t Bh[8 * 8 * 2 * 32];   // [kk][nt][reg][lane] 16KB
    uint32_t Bl[8 * 8 * 2 * 32];   // 16KB
    float w2[HID];
    float b2v;
};

__global__ __launch_bounds__(128, 3)
void k_mlp_mma(const float* __restrict__ x, const float* __restrict__ W1,
               const float* __restrict__ W2, const float* __restrict__ b2,
               const int* __restrict__ batch, int n, int ntiles) {
    __shared__ SmemMMA sm;
    const int tid  = threadIdx.x;
    const int wid  = tid >> 5;
    const int lane = tid & 31;
    const int grp  = lane >> 2;        // groupID 0..7
    const int quad = lane & 3;         // 0..3

    // --- Precompute B fragments (W1x^T, hi/lo) in fragment order -----------
    // Entry e = (kk*8 + nt)*2 + r ;  lane word covers n = nt*8+grp,
    // k = kk*16 + quad*2 + (r?8:0) + {0,1}
    for (int e = wid; e < 128; e += 4) {
        int r  = e & 1;
        int nt = (e >> 1) & 7;
        int kk = e >> 4;
        int nn = nt * 8 + grp;
        int k  = kk * 16 + quad * 2 + (r ? 8 : 0);
        float w0 = W1[k * HID + nn];
        float w1 = W1[(k + 1) * HID + nn];
        sm.Bh[e * 32 + lane] = pack_hi(w0, w1);
        sm.Bl[e * 32 + lane] = pack_lo(w0, w1);
    }
    if (tid < HID) sm.w2[tid] = W2[tid];
    if (tid == 0) sm.b2v = b2[0];
    __syncthreads();

    for (int t = blockIdx.x; t < ntiles; t += gridDim.x) {
        const int rowbase = t * 128 + wid * 32;   // this warp's 32 rows

        float c[2][8][4];
#pragma unroll
        for (int mt = 0; mt < 2; mt++)
#pragma unroll
            for (int nt = 0; nt < 8; nt++)
#pragma unroll
                for (int i = 0; i < 4; i++) c[mt][nt][i] = 0.f;

        // clamped row indices for safe loads (stores are guarded later)
        int r00 = rowbase + grp;            // mt0 rows: grp, grp+8
        int r01 = rowbase + grp + 8;
        int r10 = rowbase + grp + 16;       // mt1
        int r11 = rowbase + grp + 24;
        int c00 = min(r00, n - 1), c01 = min(r01, n - 1);
        int c10 = min(r10, n - 1), c11 = min(r11, n - 1);
        const float* x00 = x + (size_t)c00 * NF;
        const float* x01 = x + (size_t)c01 * NF;
        const float* x10 = x + (size_t)c10 * NF;
        const float* x11 = x + (size_t)c11 * NF;

#pragma unroll 2
        for (int kk = 0; kk < 8; kk++) {
            int k0 = kk * 16 + quad * 2;    // cols {k0,k0+1} and {k0+8,k0+9}
            // A fragments mt0/mt1, hi and lo
            float2 v00a = *(const float2*)(x00 + k0);
            float2 v00b = *(const float2*)(x00 + k0 + 8);
            float2 v01a = *(const float2*)(x01 + k0);
            float2 v01b = *(const float2*)(x01 + k0 + 8);
            float2 v10a = *(const float2*)(x10 + k0);
            float2 v10b = *(const float2*)(x10 + k0 + 8);
            float2 v11a = *(const float2*)(x11 + k0);
            float2 v11b = *(const float2*)(x11 + k0 + 8);

            uint32_t ah0[4], al0[4], ah1[4], al1[4];
            ah0[0] = pack_hi(v00a.x, v00a.y); al0[0] = pack_lo(v00a.x, v00a.y);
            ah0[1] = pack_hi(v01a.x, v01a.y); al0[1] = pack_lo(v01a.x, v01a.y);
            ah0[2] = pack_hi(v00b.x, v00b.y); al0[2] = pack_lo(v00b.x, v00b.y);
            ah0[3] = pack_hi(v01b.x, v01b.y); al0[3] = pack_lo(v01b.x, v01b.y);
            ah1[0] = pack_hi(v10a.x, v10a.y); al1[0] = pack_lo(v10a.x, v10a.y);
            ah1[1] = pack_hi(v11a.x, v11a.y); al1[1] = pack_lo(v11a.x, v11a.y);
            ah1[2] = pack_hi(v10b.x, v10b.y); al1[2] = pack_lo(v10b.x, v10b.y);
            ah1[3] = pack_hi(v11b.x, v11b.y); al1[3] = pack_lo(v11b.x, v11b.y);

#pragma unroll
            for (int nt = 0; nt < 8; nt++) {
                int e = (kk * 8 + nt) * 2;
                uint32_t bh0 = sm.Bh[e * 32 + lane];
                uint32_t bh1 = sm.Bh[(e + 1) * 32 + lane];
                uint32_t bl0 = sm.Bl[e * 32 + lane];
                uint32_t bl1 = sm.Bl[(e + 1) * 32 + lane];
                mma16816(c[0][nt], ah0, bh0, bh1);
                mma16816(c[1][nt], ah1, bh0, bh1);
                mma16816(c[0][nt], al0, bh0, bh1);
                mma16816(c[1][nt], al1, bh0, bh1);
                mma16816(c[0][nt], ah0, bl0, bl1);
                mma16816(c[1][nt], ah1, bl0, bl1);
            }
        }

        // --- epilogue: per row s = sum_n w2[n]*relu(c + U[batch]) ----------
#pragma unroll
        for (int mt = 0; mt < 2; mt++) {
            int ra = rowbase + mt * 16 + grp;
            int rb = ra + 8;
            int ga = batch[min(ra, n - 1)];
            int gb = batch[min(rb, n - 1)];
            const float* Ua = g_U + ga * HID;
            const float* Ub = g_U + gb * HID;
            float sa = 0.f, sb = 0.f;
#pragma unroll
            for (int nt = 0; nt < 8; nt++) {
                int n0 = nt * 8 + quad * 2;
                float2 ua = *(const float2*)(Ua + n0);
                float2 ub = *(const float2*)(Ub + n0);
                float w0 = sm.w2[n0], w1 = sm.w2[n0 + 1];
                sa = fmaf(w0, fmaxf(c[mt][nt][0] + ua.x, 0.f), sa);
                sa = fmaf(w1, fmaxf(c[mt][nt][1] + ua.y, 0.f), sa);
                sb = fmaf(w0, fmaxf(c[mt][nt][2] + ub.x, 0.f), sb);
                sb = fmaf(w1, fmaxf(c[mt][nt][3] + ub.y, 0.f), sb);
            }
            // reduce across the quad (lanes 4*grp .. 4*grp+3)
            sa += __shfl_xor_sync(0xFFFFFFFF, sa, 1);
            sa += __shfl_xor_sync(0xFFFFFFFF, sa, 2);
            sb += __shfl_xor_sync(0xFFFFFFFF, sb, 1);
            sb += __shfl_xor_sync(0xFFFFFFFF, sb, 2);
            if (quad == 0) {
                if (ra < n) g_s[ra] = sa + sm.b2v;
                if (rb < n) g_s[rb] = sb + sm.b2v;
            }
        }
    }
}

// ---------------------------------------------------------------------------
// Per-graph softmax + attn write + weighted pool (batch sorted -> contiguous)
// ---------------------------------------------------------------------------
__global__ void k_pool(const float* __restrict__ x,
                       float* __restrict__ pooled, float* __restrict__ attn) {
    int g   = blockIdx.x;
    int tid = threadIdx.x;                 // 0..127
    int s0 = g_seg[g], s1 = g_seg[g + 1];
    __shared__ float red[128];

    // pass 1: segment max
    float m = -3.0e38f;
    for (int i = s0 + tid; i < s1; i += 128) m = fmaxf(m, g_s[i]);
    red[tid] = m; __syncthreads();
#pragma unroll
    for (int off = 64; off > 0; off >>= 1) {
        if (tid < off) red[tid] = fmaxf(red[tid], red[tid + off]);
        __syncthreads();
    }
    m = red[0];
    __syncthreads();

    // pass 2: segment sum of exp
    float z = 0.f;
    for (int i = s0 + tid; i < s1; i += 128) z += __expf(g_s[i] - m);
    red[tid] = z; __syncthreads();
#pragma unroll
    for (int off = 64; off > 0; off >>= 1) {
        if (tid < off) red[tid] += red[tid + off];
        __syncthreads();
    }
    z = red[0];
    float inv = (s1 > s0) ? 1.0f / z : 0.f;
    __syncthreads();

    // attn output
    for (int i = s0 + tid; i < s1; i += 128)
        attn[i] = __expf(g_s[i] - m) * inv;

    // weighted pool: thread tid owns feature tid; 4-way unrolled for MLP
    float a0 = 0.f, a1 = 0.f, a2 = 0.f, a3 = 0.f;
    int nn = s0;
    for (; nn + 4 <= s1; nn += 4) {
        float e0 = __expf(g_s[nn + 0] - m);
        float e1 = __expf(g_s[nn + 1] - m);
        float e2 = __expf(g_s[nn + 2] - m);
        float e3 = __expf(g_s[nn + 3] - m);
        a0 = fmaf(__ldg(x + (size_t)(nn + 0) * NF + tid), e0, a0);
        a1 = fmaf(__ldg(x + (size_t)(nn + 1) * NF + tid), e1, a1);
        a2 = fmaf(__ldg(x + (size_t)(nn + 2) * NF + tid), e2, a2);
        a3 = fmaf(__ldg(x + (size_t)(nn + 3) * NF + tid), e3, a3);
    }
    for (; nn < s1; nn++)
        a0 = fmaf(__ldg(x + (size_t)nn * NF + tid), __expf(g_s[nn] - m), a0);
    pooled[g * NF + tid] = ((a0 + a1) + (a2 + a3)) * inv;
}

// ---------------------------------------------------------------------------
extern "C" void kernel_launch(void* const* d_in, const int* in_sizes, int n_in,
                              void* d_out, int out_size) {
    const float* x     = (const float*)d_in[0];
    const float* u     = (const float*)d_in[1];
    const int*   batch = (const int*)  d_in[2];
    const float* W1    = (const float*)d_in[3];
    const float* b1    = (const float*)d_in[4];
    const float* W2    = (const float*)d_in[5];
    const float* b2    = (const float*)d_in[6];

    float* pooled = (float*)d_out;                     // [16384, 128]
    float* attn   = (float*)d_out + NGRAPHS * NF;      // [1e6]

    int n = in_sizes[2];
    int ntiles = (n + 127) / 128;

    k_segstart<<<(NGRAPHS + 1 + 255) / 256, 256>>>(batch, n);
    k_uproj<<<NGRAPHS, GF>>>(u, W1, b1);
    k_mlp_mma<<<444, 128>>>(x, W1, W2, b2, batch, n, ntiles);
    k_pool<<<NGRAPHS, 128>>>(x, pooled, attn);
}